// round 1
// baseline (speedup 1.0000x reference)
#include <cuda_runtime.h>
#include <math.h>

#define B_ 1024
#define T_ 16
#define D_ 1024
#define H_ 2048
#define O_ 1024

// ---------------- scratch (device globals; no allocation allowed) ----------
__device__ float g_inp[B_ * T_ * H_];   // hoisted input projection, row (b*T+t)
__device__ float g_pre[B_ * H_];        // GEMM pre-activation / current
__device__ float g_tmp[B_ * H_];        // s = ctx+rec  /  gated
__device__ float g_ctx[B_ * H_];
__device__ float g_rec[B_ * H_];
__device__ float g_attr[B_ * H_];
__device__ float g_spk[B_ * H_];

// ---------------- fp32 SGEMM: C = alpha*(A1@B1 [+ A2@B2]) + bias1 [+ bias2] -
// A row-major with leading dim lda, B row-major [K,N] contiguous (ldb=N),
// C row-major ldc. All dims multiples of tile sizes (no bounds checks).
__global__ void __launch_bounds__(256) sgemm_kernel(
    const float* __restrict__ A1, int lda1,
    const float* __restrict__ B1,
    const float* __restrict__ A2, int lda2,
    const float* __restrict__ B2,
    const float* __restrict__ bias1, const float* __restrict__ bias2,
    float* __restrict__ C, int ldc,
    int M, int N, int K, float alpha)
{
    const int BM = 128, BN = 128, BK = 16;
    __shared__ float As[BK][BM];
    __shared__ float Bs[BK][BN];

    const int bm = blockIdx.y * BM;
    const int bn = blockIdx.x * BN;
    const int tid = threadIdx.x;
    const int tr = tid / 16;          // 0..15, row-thread
    const int tc = tid % 16;          // 0..15, col-thread

    // load mapping
    const int a_r = tid / 4;          // 0..63 (two passes of 64 rows)
    const int a_c = (tid % 4) * 4;    // 0,4,8,12
    const int b_r = tid / 32;         // 0..7 (two passes of 8 rows)
    const int b_c = (tid % 32) * 4;   // 0..124

    float acc[8][8];
#pragma unroll
    for (int i = 0; i < 8; i++)
#pragma unroll
        for (int j = 0; j < 8; j++) acc[i][j] = 0.0f;

    const int npass = (A2 != nullptr) ? 2 : 1;
    for (int pass = 0; pass < npass; pass++) {
        const float* A  = pass ? A2 : A1;
        const float* Bm = pass ? B2 : B1;
        const int lda   = pass ? lda2 : lda1;

        for (int k0 = 0; k0 < K; k0 += BK) {
            // load A tile (transposed into smem)
#pragma unroll
            for (int i = 0; i < 2; i++) {
                int r = a_r + i * 64;
                float4 v = *(const float4*)(A + (long)(bm + r) * lda + k0 + a_c);
                As[a_c + 0][r] = v.x;
                As[a_c + 1][r] = v.y;
                As[a_c + 2][r] = v.z;
                As[a_c + 3][r] = v.w;
            }
            // load B tile
#pragma unroll
            for (int i = 0; i < 2; i++) {
                int r = b_r + i * 8;
                float4 v = *(const float4*)(Bm + (long)(k0 + r) * N + bn + b_c);
                *(float4*)&Bs[r][b_c] = v;
            }
            __syncthreads();

#pragma unroll
            for (int kk = 0; kk < BK; kk++) {
                float4 a0 = *(const float4*)&As[kk][tr * 8];
                float4 a1 = *(const float4*)&As[kk][tr * 8 + 4];
                float4 b0 = *(const float4*)&Bs[kk][tc * 8];
                float4 b1 = *(const float4*)&Bs[kk][tc * 8 + 4];
                float a[8] = {a0.x, a0.y, a0.z, a0.w, a1.x, a1.y, a1.z, a1.w};
                float b[8] = {b0.x, b0.y, b0.z, b0.w, b1.x, b1.y, b1.z, b1.w};
#pragma unroll
                for (int i = 0; i < 8; i++)
#pragma unroll
                    for (int j = 0; j < 8; j++)
                        acc[i][j] = fmaf(a[i], b[j], acc[i][j]);
            }
            __syncthreads();
        }
    }

    // epilogue
    const int row0 = bm + tr * 8;
    const int col0 = bn + tc * 8;
    float bias[8];
#pragma unroll
    for (int j = 0; j < 8; j++) {
        float v = bias1[col0 + j];
        if (bias2 != nullptr) v += bias2[col0 + j];
        bias[j] = v;
    }
#pragma unroll
    for (int i = 0; i < 8; i++) {
        float4 o0, o1;
        o0.x = alpha * acc[i][0] + bias[0];
        o0.y = alpha * acc[i][1] + bias[1];
        o0.z = alpha * acc[i][2] + bias[2];
        o0.w = alpha * acc[i][3] + bias[3];
        o1.x = alpha * acc[i][4] + bias[4];
        o1.y = alpha * acc[i][5] + bias[5];
        o1.z = alpha * acc[i][6] + bias[6];
        o1.w = alpha * acc[i][7] + bias[7];
        *(float4*)(C + (long)(row0 + i) * ldc + col0)     = o0;
        *(float4*)(C + (long)(row0 + i) * ldc + col0 + 4) = o1;
    }
}

// ---------------- elementwise kernels --------------------------------------
__inline__ __device__ float warpsum(float v) {
#pragma unroll
    for (int o = 16; o > 0; o >>= 1) v += __shfl_xor_sync(0xffffffffu, v, o);
    return v;
}

// step1: update=tanh(pre); rec = 0.9*rec + 0.1*update; ctx = LN(rec)*gamma+beta;
//        s = ctx + rec.  One block per row (B rows, H=2048 cols, 256 threads).
__global__ void __launch_bounds__(256) step1_kernel(
    const float* __restrict__ pre, float* __restrict__ rec,
    float* __restrict__ ctx, float* __restrict__ s,
    const float* __restrict__ gamma, const float* __restrict__ beta)
{
    const int row = blockIdx.x;
    const float* p = pre + (long)row * H_;
    float* r = rec + (long)row * H_;

    float vals[8];
    float sum = 0.f, sumsq = 0.f;
#pragma unroll
    for (int i = 0; i < 8; i++) {
        int h = threadIdx.x + i * 256;
        float u = tanhf(p[h]);
        float nr = 0.9f * r[h] + 0.1f * u;
        r[h] = nr;
        vals[i] = nr;
        sum += nr;
        sumsq += nr * nr;
    }
    float s1 = warpsum(sum), s2 = warpsum(sumsq);
    __shared__ float sh[16];
    int warp = threadIdx.x >> 5, lane = threadIdx.x & 31;
    if (lane == 0) { sh[warp] = s1; sh[8 + warp] = s2; }
    __syncthreads();
    if (threadIdx.x == 0) {
        float a = 0.f, b = 0.f;
#pragma unroll
        for (int i = 0; i < 8; i++) { a += sh[i]; b += sh[8 + i]; }
        sh[0] = a; sh[8] = b;
    }
    __syncthreads();
    const float mean = sh[0] * (1.0f / H_);
    const float var  = sh[8] * (1.0f / H_) - mean * mean;
    const float inv  = rsqrtf(var + 1e-5f);
#pragma unroll
    for (int i = 0; i < 8; i++) {
        int h = threadIdx.x + i * 256;
        float c = (vals[i] - mean) * inv * gamma[h] + beta[h];
        ctx[(long)row * H_ + h] = c;
        s[(long)row * H_ + h]   = c + vals[i];
    }
}

// step2: g = sigmoid(pre2); gated = g*ctx + (1-g)*rec   (in-place into tmp)
__global__ void __launch_bounds__(256) step2_kernel(
    const float* __restrict__ pre, const float* __restrict__ ctx,
    const float* __restrict__ rec, float* __restrict__ gated)
{
    long i = (long)blockIdx.x * blockDim.x + threadIdx.x;  // over B*H/4
    const float4 p = ((const float4*)pre)[i];
    const float4 c = ((const float4*)ctx)[i];
    const float4 r = ((const float4*)rec)[i];
    float4 o;
    float g;
    g = 1.0f / (1.0f + expf(-p.x)); o.x = g * c.x + (1.0f - g) * r.x;
    g = 1.0f / (1.0f + expf(-p.y)); o.y = g * c.y + (1.0f - g) * r.y;
    g = 1.0f / (1.0f + expf(-p.z)); o.z = g * c.z + (1.0f - g) * r.z;
    g = 1.0f / (1.0f + expf(-p.w)); o.w = g * c.w + (1.0f - g) * r.w;
    ((float4*)gated)[i] = o;
}

// step3: v = attr + (cur-attr)/2; spike = v>1; attr = v - spike; spk += spike
__global__ void __launch_bounds__(256) step3_kernel(
    const float* __restrict__ cur, float* __restrict__ attr,
    float* __restrict__ spk)
{
    long i = (long)blockIdx.x * blockDim.x + threadIdx.x;  // over B*H/4
    const float4 c = ((const float4*)cur)[i];
    float4 a = ((float4*)attr)[i];
    float4 sp = ((float4*)spk)[i];
    float v, s;
    v = a.x + (c.x - a.x) * 0.5f; s = (v > 1.0f) ? 1.0f : 0.0f; a.x = v - s; sp.x += s;
    v = a.y + (c.y - a.y) * 0.5f; s = (v > 1.0f) ? 1.0f : 0.0f; a.y = v - s; sp.y += s;
    v = a.z + (c.z - a.z) * 0.5f; s = (v > 1.0f) ? 1.0f : 0.0f; a.z = v - s; sp.z += s;
    v = a.w + (c.w - a.w) * 0.5f; s = (v > 1.0f) ? 1.0f : 0.0f; a.w = v - s; sp.w += s;
    ((float4*)attr)[i] = a;
    ((float4*)spk)[i]  = sp;
}

__global__ void __launch_bounds__(256) init_kernel(
    float* __restrict__ rec, float* __restrict__ attr, float* __restrict__ spk)
{
    long i = (long)blockIdx.x * blockDim.x + threadIdx.x;  // over B*H/4
    float4 z = make_float4(0.f, 0.f, 0.f, 0.f);
    ((float4*)rec)[i]  = z;
    ((float4*)attr)[i] = z;
    ((float4*)spk)[i]  = z;
}

// copy rec, attr into the output tail
__global__ void __launch_bounds__(256) tail_kernel(
    const float* __restrict__ rec, const float* __restrict__ attr,
    float* __restrict__ out)
{
    long i = (long)blockIdx.x * blockDim.x + threadIdx.x;  // over B*H/4
    ((float4*)out)[i]                  = ((const float4*)rec)[i];
    ((float4*)(out + (long)B_ * H_))[i] = ((const float4*)attr)[i];
}

// ---------------- launch ----------------------------------------------------
extern "C" void kernel_launch(void* const* d_in, const int* in_sizes, int n_in,
                              void* d_out, int out_size)
{
    const float* x       = (const float*)d_in[0];
    const float* Wp      = (const float*)d_in[1];
    const float* bp      = (const float*)d_in[2];
    const float* Wfc     = (const float*)d_in[3];
    const float* bfc     = (const float*)d_in[4];
    const float* gamma   = (const float*)d_in[5];
    const float* beta_ln = (const float*)d_in[6];
    const float* Wg      = (const float*)d_in[7];
    const float* bg      = (const float*)d_in[8];
    const float* Wenc    = (const float*)d_in[9];
    const float* benc    = (const float*)d_in[10];
    const float* Wrec    = (const float*)d_in[11];
    const float* brec    = (const float*)d_in[12];
    const float* Wro     = (const float*)d_in[13];
    const float* bro     = (const float*)d_in[14];
    float* out = (float*)d_out;

    float *inp, *pre, *tmp, *ctx, *rec, *attr, *spk;
    cudaGetSymbolAddress((void**)&inp,  g_inp);
    cudaGetSymbolAddress((void**)&pre,  g_pre);
    cudaGetSymbolAddress((void**)&tmp,  g_tmp);
    cudaGetSymbolAddress((void**)&ctx,  g_ctx);
    cudaGetSymbolAddress((void**)&rec,  g_rec);
    cudaGetSymbolAddress((void**)&attr, g_attr);
    cudaGetSymbolAddress((void**)&spk,  g_spk);

    const int EW_BLOCKS = (B_ * H_ / 4) / 256;  // 2048

    init_kernel<<<EW_BLOCKS, 256>>>(rec, attr, spk);

    // input projection: [B*T, D] @ [D, H] -> g_inp [B*T, H]
    {
        dim3 grid(H_ / 128, (B_ * T_) / 128);
        sgemm_kernel<<<grid, 256>>>(x, D_, Wp, nullptr, 0, nullptr,
                                    bp, nullptr, inp, H_,
                                    B_ * T_, H_, D_, 1.0f);
    }

    dim3 gstep(H_ / 128, B_ / 128);  // (16, 8)
    for (int t = 0; t < T_; t++) {
        const float* At = inp + (long)t * H_;  // row stride T*H
        // GEMM1: pre = inp_t @ Wfc + bfc
        sgemm_kernel<<<gstep, 256>>>(At, T_ * H_, Wfc, nullptr, 0, nullptr,
                                     bfc, nullptr, pre, H_, B_, H_, H_, 1.0f);
        // tanh + rec update + LayerNorm + s
        step1_kernel<<<B_, 256>>>(pre, rec, ctx, tmp, gamma, beta_ln);
        // GEMM2: pre = s @ Wg + bg
        sgemm_kernel<<<gstep, 256>>>(tmp, H_, Wg, nullptr, 0, nullptr,
                                     bg, nullptr, pre, H_, B_, H_, H_, 1.0f);
        // gate
        step2_kernel<<<EW_BLOCKS, 256>>>(pre, ctx, rec, tmp);
        // GEMM3 (fused dual): pre = gated @ Wenc + attr @ Wrec + benc + brec
        sgemm_kernel<<<gstep, 256>>>(tmp, H_, Wenc, attr, H_, Wrec,
                                     benc, brec, pre, H_, B_, H_, H_, 1.0f);
        // LIF update + spike accumulation
        step3_kernel<<<EW_BLOCKS, 256>>>(pre, attr, spk);
    }

    // readout: out = (spk/T) @ Wro + bro
    {
        dim3 grid(O_ / 128, B_ / 128);
        sgemm_kernel<<<grid, 256>>>(spk, H_, Wro, nullptr, 0, nullptr,
                                    bro, nullptr, out, O_,
                                    B_, O_, H_, 1.0f / T_);
    }
    // rec, attr outputs
    tail_kernel<<<EW_BLOCKS, 256>>>(rec, attr, out + (long)B_ * O_);
}